// round 12
// baseline (speedup 1.0000x reference)
#include <cuda_runtime.h>
#include <cuda_fp16.h>
#include <cstdint>

#define BATCH 256
#define TSEQ  2048
#define DH    512
#define STEPS 2040
#define DIN   384

__device__ float g_hx[(size_t)BATCH * STEPS * DH];

__device__ __forceinline__ unsigned su32(const void* p) {
    return (unsigned)__cvta_generic_to_shared(p);
}
__device__ __forceinline__ void ldsm4(unsigned* r, unsigned a) {
    asm volatile("ldmatrix.sync.aligned.m8n8.x4.shared.b16 {%0,%1,%2,%3}, [%4];"
                 : "=r"(r[0]), "=r"(r[1]), "=r"(r[2]), "=r"(r[3]) : "r"(a));
}
__device__ __forceinline__ void ldsm2(unsigned& r0, unsigned& r1, unsigned a) {
    asm volatile("ldmatrix.sync.aligned.m8n8.x2.shared.b16 {%0,%1}, [%2];"
                 : "=r"(r0), "=r"(r1) : "r"(a));
}
__device__ __forceinline__ void mma16816(float* c, const unsigned* a, unsigned b0, unsigned b1) {
    asm volatile("mma.sync.aligned.m16n8k16.row.col.f32.f16.f16.f32 "
                 "{%0,%1,%2,%3}, {%4,%5,%6,%7}, {%8,%9}, {%0,%1,%2,%3};"
                 : "+f"(c[0]), "+f"(c[1]), "+f"(c[2]), "+f"(c[3])
                 : "r"(a[0]), "r"(a[1]), "r"(a[2]), "r"(a[3]), "r"(b0), "r"(b1));
}
__device__ __forceinline__ float tanh_fast(float v) {
    float r; asm("tanh.approx.f32 %0, %1;" : "=f"(r) : "f"(v)); return r;
}
__device__ __forceinline__ float2 h2f2(unsigned u) {
    __half2 h = *(__half2*)&u; return __half22float2(h);
}

// ===========================================================================
// Phase A: Hx = Xwin[128t x 256k] @ W1x^T, fp16 mma  (R9-passing version)
// ===========================================================================
#define WS_LD 264
#define CB_LD 132
#define XSP   5408

__global__ void __launch_bounds__(256, 2)
narx_hx(const float* __restrict__ x, const float* __restrict__ W1,
        const float* __restrict__ b1)
{
    extern __shared__ unsigned char smraw[];
    __half* xs = (__half*)smraw;
    __half* ws = (__half*)(smraw + XSP * 2);
    float*  cb = (float*)(smraw + XSP * 2);

    const int tid = threadIdx.x, warp = tid >> 5, lane = tid & 31;
    const int wm = warp & 1, wn = warp >> 1;
    const int t0 = blockIdx.x * 128, J0 = blockIdx.y * 128, b = blockIdx.z;

    {
        const float* xb = x + (size_t)b * (TSEQ * 32) + (size_t)t0 * 32;
        const int lim = TSEQ * 32 - t0 * 32;
        for (int i = tid; i < 4320; i += 256) {
            float v = (i < lim) ? xb[i] : 0.0f;
            xs[(i >> 5) * 40 + (i & 31)] = __float2half_rn(v);
        }
    }
    for (int idx = tid; idx < 128 * 128; idx += 256) {
        int j = idx >> 7, k2 = (idx & 127) << 1;
        const float* w = W1 + (size_t)(J0 + j) * DIN + k2;
        *(__half2*)(ws + j * WS_LD + k2) = __floats2half2_rn(w[0], w[1]);
    }
    __syncthreads();

    float c[4][4][4];
    #pragma unroll
    for (int i = 0; i < 4; i++)
        #pragma unroll
        for (int j = 0; j < 4; j++)
            #pragma unroll
            for (int r = 0; r < 4; r++) c[i][j][r] = 0.0f;

    const unsigned xsb = su32(xs), wsb = su32(ws);
    const int mat = lane >> 3, lrow = lane & 7;

    #pragma unroll 4
    for (int ks = 0; ks < 16; ++ks) {
        unsigned a[4][4], b0[4], b1[4];
        const int col = ks * 16 + (mat >> 1) * 8;
        const int ce  = (col >> 5) * 40 + (col & 31);
        #pragma unroll
        for (int mt = 0; mt < 4; ++mt) {
            int row = wm * 64 + mt * 16 + (mat & 1) * 8 + lrow;
            ldsm4(a[mt], xsb + 2u * (unsigned)(row * 40 + ce));
        }
        const int bcol = ks * 16 + ((lane >> 3) & 1) * 8;
        #pragma unroll
        for (int nt = 0; nt < 4; ++nt) {
            int br = wn * 32 + nt * 8 + lrow;
            ldsm2(b0[nt], b1[nt], wsb + 2u * (unsigned)(br * WS_LD + bcol));
        }
        #pragma unroll
        for (int mt = 0; mt < 4; ++mt)
            #pragma unroll
            for (int nt = 0; nt < 4; ++nt)
                mma16816(c[mt][nt], a[mt], b0[nt], b1[nt]);
    }

    __syncthreads();
    {
        const int g = lane >> 2, tq = lane & 3;
        #pragma unroll
        for (int mt = 0; mt < 4; ++mt)
            #pragma unroll
            for (int nt = 0; nt < 4; ++nt) {
                int m0 = wm * 64 + mt * 16 + g, n0 = wn * 32 + nt * 8 + tq * 2;
                *(float2*)(cb + m0 * CB_LD + n0) = make_float2(c[mt][nt][0], c[mt][nt][1]);
                *(float2*)(cb + (m0 + 8) * CB_LD + n0) = make_float2(c[mt][nt][2], c[mt][nt][3]);
            }
    }
    __syncthreads();
    {
        const float4 bv = *(const float4*)(b1 + J0 + lane * 4);
        #pragma unroll 4
        for (int rr = 0; rr < 16; ++rr) {
            int row = warp * 16 + rr, t = t0 + row;
            if (t < STEPS) {
                float4 v = *(float4*)(cb + row * CB_LD + lane * 4);
                v.x += bv.x; v.y += bv.y; v.z += bv.z; v.w += bv.w;
                *(float4*)(g_hx + ((size_t)b * STEPS + t) * DH + J0 + lane * 4) = v;
            }
        }
    }
}

// ===========================================================================
// Phase B: 128 blocks x 512 threads, 2 batch rows. Feedback GEMM on tensor
// pipe (Wf frags in regs, y ring in smem). Layer2: W2 fp16 regs, h half2
// pairs in padded smem, warp-per-(2m x 2rows), shuffle reduce. 2 barriers.
// ===========================================================================
#define YLD 136
__global__ void __launch_bounds__(512, 1)
narx_recur(const float* __restrict__ W1, const float* __restrict__ W2,
           const float* __restrict__ b2, float* __restrict__ out)
{
    extern __shared__ unsigned char smraw[];
    __half*   wf  = (__half*)smraw;                 // 512*136 halves (staging)
    __half*   ys  = (__half*)(smraw + 139264);      // 8*136 (y ring, rows=n)
    unsigned* sh2 = (unsigned*)(smraw + 141440);    // 640 half2 (h pairs, padded)

    const int tid = threadIdx.x, warp = tid >> 5, lane = tid & 31;
    const int b0 = blockIdx.x * 2;
    const int jb = warp * 32;
    const int mat = lane >> 3, lrow = lane & 7;

    // ---- one-time staging ----
    for (int idx = tid; idx < 512 * 64; idx += 512) {
        int j = idx >> 6, q2 = (idx & 63) << 1;
        const float* s = W1 + (size_t)j * DIN + 256 + q2;
        *(__half2*)(wf + j * YLD + q2) = __floats2half2_rn(s[0], s[1]);
    }
    for (int idx = tid; idx < 8 * YLD; idx += 512) ys[idx] = __float2half_rn(0.0f);
    __syncthreads();

    // Wf A-fragments resident in registers (2 mt x 8 kt x 4)
    unsigned wfr[2][8][4];
    {
        const unsigned wfb = su32(wf);
        #pragma unroll
        for (int mt = 0; mt < 2; ++mt)
            #pragma unroll
            for (int kt = 0; kt < 8; ++kt) {
                int j = jb + mt * 16 + (mat & 1) * 8 + lrow;
                int q = kt * 16 + (mat >> 1) * 8;
                ldsm4(wfr[mt][kt], wfb + 2u * (unsigned)(j * YLD + q));
            }
    }

    // W2 fp16 register copy: thread covers m0=2*warp, m1=2*warp+1,
    // j in [lane*16, lane*16+16)
    const int m0 = warp * 2, m1 = m0 + 1, jl0 = lane * 16;
    unsigned w2a[8], w2b[8];
    #pragma unroll
    for (int p = 0; p < 8; ++p) {
        const float* wa = W2 + (size_t)m0 * DH + jl0 + p * 2;
        const float* wb = W2 + (size_t)m1 * DH + jl0 + p * 2;
        __half2 ha = __floats2half2_rn(wa[0], wa[1]);
        __half2 hb = __floats2half2_rn(wb[0], wb[1]);
        w2a[p] = *(unsigned*)&ha; w2b[p] = *(unsigned*)&hb;
    }
    const float bz0 = b2[m0], bz1 = b2[m1];

    const float* hx0 = g_hx + (size_t)b0 * STEPS * DH;
    const float* hx1 = hx0 + (size_t)STEPS * DH;
    const int m8 = lane >> 2;
    const int ja = jb + m8, jc = jb + 16 + m8;
    const int yn = lane >> 2, yk = (lane & 3) * 2;

    float cur[8];
    cur[0] = __ldcs(hx0 + ja);      cur[1] = __ldcs(hx1 + ja);
    cur[2] = __ldcs(hx0 + ja + 8);  cur[3] = __ldcs(hx1 + ja + 8);
    cur[4] = __ldcs(hx0 + jc);      cur[5] = __ldcs(hx1 + jc);
    cur[6] = __ldcs(hx0 + jc + 8);  cur[7] = __ldcs(hx1 + jc + 8);

    for (int i = 0; i < STEPS; ++i) {
        float c0[4] = {cur[0], cur[1], cur[2], cur[3]};
        float c1[4] = {cur[4], cur[5], cur[6], cur[7]};

        if (i + 1 < STEPS) {
            const float* p0 = hx0 + (size_t)(i + 1) * DH;
            const float* p1 = hx1 + (size_t)(i + 1) * DH;
            cur[0] = __ldcs(p0 + ja);     cur[1] = __ldcs(p1 + ja);
            cur[2] = __ldcs(p0 + ja + 8); cur[3] = __ldcs(p1 + ja + 8);
            cur[4] = __ldcs(p0 + jc);     cur[5] = __ldcs(p1 + jc);
            cur[6] = __ldcs(p0 + jc + 8); cur[7] = __ldcs(p1 + jc + 8);
        }

        // feedback GEMM, y ring addressing (slot of age-d block = (i+d)&3)
        #pragma unroll
        for (int kt = 0; kt < 8; ++kt) {
            int off = (((i + (kt >> 1)) & 3) << 5) + ((kt & 1) << 4);
            unsigned bb0 = *(const unsigned*)(ys + yn * YLD + off + yk);
            unsigned bb1 = *(const unsigned*)(ys + yn * YLD + off + 8 + yk);
            mma16816(c0, wfr[0][kt], bb0, bb1);
            mma16816(c1, wfr[1][kt], bb0, bb1);
        }

        // tanh + store h as half2(row0,row1), padded layout u(j)=j+4*(j>>4)
        if ((lane & 3) == 0) {
            __half2 p0 = __floats2half2_rn(tanh_fast(c0[0]), tanh_fast(c0[1]));
            __half2 p1 = __floats2half2_rn(tanh_fast(c0[2]), tanh_fast(c0[3]));
            __half2 p2 = __floats2half2_rn(tanh_fast(c1[0]), tanh_fast(c1[1]));
            __half2 p3 = __floats2half2_rn(tanh_fast(c1[2]), tanh_fast(c1[3]));
            sh2[ja     + ((ja    ) >> 4) * 4] = *(unsigned*)&p0;
            sh2[ja + 8 + ((ja + 8) >> 4) * 4] = *(unsigned*)&p1;
            sh2[jc     + ((jc    ) >> 4) * 4] = *(unsigned*)&p2;
            sh2[jc + 8 + ((jc + 8) >> 4) * 4] = *(unsigned*)&p3;
        }
        __syncthreads();                            // (A) h ready

        // layer 2: lane covers j in [16*lane, +16) for outputs (m0,m1)x(r0,r1)
        float a00 = 0.f, a01 = 0.f, a10 = 0.f, a11 = 0.f;
        {
            const unsigned* hb = sh2 + 20 * lane;
            uint4 hv0 = *(const uint4*)(hb);
            uint4 hv1 = *(const uint4*)(hb + 4);
            uint4 hv2 = *(const uint4*)(hb + 8);
            uint4 hv3 = *(const uint4*)(hb + 12);
            unsigned hh[16] = {hv0.x, hv0.y, hv0.z, hv0.w, hv1.x, hv1.y, hv1.z, hv1.w,
                               hv2.x, hv2.y, hv2.z, hv2.w, hv3.x, hv3.y, hv3.z, hv3.w};
            #pragma unroll
            for (int p = 0; p < 8; ++p) {
                float2 hA = h2f2(hh[2 * p]);
                float2 hB = h2f2(hh[2 * p + 1]);
                float2 wA = h2f2(w2a[p]);
                float2 wB = h2f2(w2b[p]);
                a00 = fmaf(wA.x, hA.x, a00); a00 = fmaf(wA.y, hB.x, a00);
                a01 = fmaf(wA.x, hA.y, a01); a01 = fmaf(wA.y, hB.y, a01);
                a10 = fmaf(wB.x, hA.x, a10); a10 = fmaf(wB.y, hB.x, a10);
                a11 = fmaf(wB.x, hA.y, a11); a11 = fmaf(wB.y, hB.y, a11);
            }
        }
        #pragma unroll
        for (int off = 16; off >= 1; off >>= 1) {
            a00 += __shfl_xor_sync(0xffffffffu, a00, off);
            a01 += __shfl_xor_sync(0xffffffffu, a01, off);
            a10 += __shfl_xor_sync(0xffffffffu, a10, off);
            a11 += __shfl_xor_sync(0xffffffffu, a11, off);
        }
        if (lane == 0) {
            float o00 = 1.0f / (1.0f + __expf(-(a00 + bz0)));
            float o01 = 1.0f / (1.0f + __expf(-(a01 + bz0)));
            float o10 = 1.0f / (1.0f + __expf(-(a10 + bz1)));
            float o11 = 1.0f / (1.0f + __expf(-(a11 + bz1)));
            int slot = (i & 3) << 5;
            ys[slot + m0]       = __float2half_rn(o00);
            ys[YLD + slot + m0] = __float2half_rn(o01);
            ys[slot + m1]       = __float2half_rn(o10);
            ys[YLD + slot + m1] = __float2half_rn(o11);
            size_t ob = ((size_t)b0 * STEPS + i) * 32;
            out[ob + m0] = o00;
            out[ob + m1] = o10;
            out[ob + (size_t)STEPS * 32 + m0] = o01;
            out[ob + (size_t)STEPS * 32 + m1] = o11;
        }
        __syncthreads();                            // (C) y ready
    }
}

extern "C" void kernel_launch(void* const* d_in, const int* in_sizes, int n_in,
                              void* d_out, int out_size)
{
    const float* x  = (const float*)d_in[0];
    const float* W1 = (const float*)d_in[1];
    const float* b1 = (const float*)d_in[2];
    const float* W2 = (const float*)d_in[3];
    const float* b2 = (const float*)d_in[4];
    float* out = (float*)d_out;
    (void)in_sizes; (void)n_in; (void)out_size;

    constexpr size_t smA = XSP * 2 + 128 * WS_LD * 2;   // 78,400 B
    constexpr size_t smB = 141440 + 640 * 4;            // 144,000 B

    cudaFuncSetAttribute(narx_hx, cudaFuncAttributeMaxDynamicSharedMemorySize, (int)smA);
    cudaFuncSetAttribute(narx_recur, cudaFuncAttributeMaxDynamicSharedMemorySize, (int)smB);

    dim3 gA(16, 4, 256);
    narx_hx<<<gA, 256, smA>>>(x, W1, b1);
    narx_recur<<<128, 512, smB>>>(W1, W2, b2, out);
}